// round 9
// baseline (speedup 1.0000x reference)
#include <cuda_runtime.h>
#include <cuda_fp16.h>
#include <mma.h>
#include <cstdint>

using namespace nvcuda;

#define NN 50000
#define EE 800000
#define DD 128
#define EPSI 0.001f
#define NCH 36                     // K = 2304 = 36 * 64 (18 per weight set)
#define MT 128                     // M tile rows per CTA
#define NTHR 512
#define LDAE 72                    // A tile ld (halfs), 144 B
#define LDBE 136                   // B tile ld (halfs), 272 B
#define LDCE 136                   // epilogue staging ld (halfs)
#define A_TILE (MT * LDAE * 2)     // 18432 B
#define B_TILE (64 * LDBE * 2)     // 17408 B
#define NBUF 4                     // B pipeline depth
#define KAN_SMEM (2 * A_TILE + NBUF * B_TILE)  // 106496 B

// ---------------- device scratch ----------------------------------------------
__device__ float g_x[(size_t)NN * DD];
__device__ __half2 g_xh[(size_t)NN * 64];
__device__ __half2 g_aggh[2][(size_t)NN * 64];
__device__ float g_deg[NN];
__device__ __half g_wt[2 * 1152 * DD];  // [set][k][o], k-major (36 chunks of 64 k)
__device__ int g_is64;

// ---------------- helpers ------------------------------------------------------
__device__ __forceinline__ uint32_t smem_u32(const void* p) {
    uint32_t a;
    asm("{ .reg .u64 t; cvta.to.shared.u64 t, %1; cvt.u32.u64 %0, t; }" : "=r"(a) : "l"(p));
    return a;
}
__device__ __forceinline__ void cp_async16(uint32_t dst, const void* src) {
    asm volatile("cp.async.cg.shared.global [%0], [%1], 16;" :: "r"(dst), "l"(src));
}
__device__ __forceinline__ void cp_commit() { asm volatile("cp.async.commit_group;"); }
__device__ __forceinline__ void cp_wait2() { asm volatile("cp.async.wait_group 2;"); }
__device__ __forceinline__ unsigned pack2h(float a, float b) {
    __half2 h = __floats2half2_rn(a, b);
    return *(unsigned*)&h;
}
__device__ __forceinline__ int get_idx(const void* p, long long e) {
    if (g_is64) return (int)((const long long*)p)[e];
    return ((const int*)p)[e];
}

// ---------------- local cubic B-spline: 4 nonzero bases -> 4 packed u32 -------
__device__ __forceinline__ void bs8_fast(float x, uint32_t* w) {
    float T = fmaf(x, 2.5f, 5.5f);
    T = fminf(fmaxf(T, 2.0f), 8.999f);
    float jf = floorf(T);
    float u = T - jf;
    int s = (int)jf - 3;
    float u2 = u * u, u3 = u2 * u;
    float v0 = fmaf(u, -0.5f, 1.0f / 6.0f);
    v0 = fmaf(u2, 0.5f, v0);
    v0 = fmaf(u3, -1.0f / 6.0f, v0);
    float v1 = fmaf(u2, -1.0f, 2.0f / 3.0f);
    v1 = fmaf(u3, 0.5f, v1);
    float v2 = fmaf(u, 0.5f, 1.0f / 6.0f);
    v2 = fmaf(u2, 0.5f, v2);
    v2 = fmaf(u3, -0.5f, v2);
    float v3 = u3 * (1.0f / 6.0f);
    uint32_t p01 = pack2h(v0, v1), p23 = pack2h(v2, v3);
    int sh = (s & 1) << 4;
    int p = s >> 1;
    uint32_t r0 = p01 << sh;
    uint32_t r1 = __funnelshift_l(p01, p23, sh);
    uint32_t r2 = sh ? (p23 >> 16) : 0u;
#pragma unroll
    for (int i = 0; i < 4; i++) {
        int d = i - p;
        w[i] = (d == 0) ? r0 : (d == 1) ? r1 : (d == 2) ? r2 : 0u;
    }
}

// ---------------- setup: x->half, clear agg/deg, weights->half, detect ---------
#define N_XH ((long long)NN * 32)
#define N_CLR ((long long)2 * NN * 16)
#define N_W ((long long)2 * 1152 * 128)
#define N_SETUP (N_XH + N_CLR + N_W + NN + 1)

__global__ void setup_kernel(const float* __restrict__ x,
                             const float* __restrict__ bwl, const float* __restrict__ swl,
                             const float* __restrict__ bwc, const float* __restrict__ swc,
                             const int* __restrict__ ei) {
    long long idx = (long long)blockIdx.x * 256 + threadIdx.x;
    if (idx < N_XH) {
        float4 v = ((const float4*)x)[idx];
        __half2 h0 = __floats2half2_rn(v.x, v.y);
        __half2 h1 = __floats2half2_rn(v.z, v.w);
        ((uint2*)g_xh)[idx] = make_uint2(*(uint32_t*)&h0, *(uint32_t*)&h1);
    } else if (idx < N_XH + N_CLR) {
        ((uint4*)g_aggh)[idx - N_XH] = make_uint4(0, 0, 0, 0);
    } else if (idx < N_XH + N_CLR + N_W) {
        long long r = idx - N_XH - N_CLR;
        int set = (int)(r / (1152 * 128));
        int q = (int)(r - (long long)set * (1152 * 128));
        int k = q >> 7, o = q & 127;
        const float* bw = set ? bwc : bwl;
        const float* sw = set ? swc : swl;
        float v = (k < DD) ? bw[o * DD + k] : sw[(long long)o * 1024 + (k - DD)];
        g_wt[r] = __float2half(v);
    } else if (idx < N_XH + N_CLR + N_W + NN) {
        g_deg[idx - N_XH - N_CLR - N_W] = 0.0f;
    } else if (idx == N_XH + N_CLR + N_W + NN) {
        int is64 = 1;
        for (int k = 0; k < 16; k++)
            if (ei[2 * k + 1] != 0) { is64 = 0; break; }
        g_is64 = is64;
    }
}

__global__ void deg_kernel(const void* __restrict__ ei) {
    int e = blockIdx.x * blockDim.x + threadIdx.x;
    if (e < EE) atomicAdd(&g_deg[get_idx(ei, (long long)EE + e)], 1.0f);
}

// ---------------- fused dual-branch KAN kernel (MT=128, 512 thr, fp16 acc) -----
// out = xin + EPSI * ( featL(xh)@WL + featC(agg)@WC )
// Fully-unrolled chunk loop; 4-stage cp.async pipeline on B tiles.
template <int WH>
__global__ __launch_bounds__(NTHR, 2) void kan_fused(const __half2* __restrict__ hh,
                                                     const __half2* __restrict__ agg,
                                                     const float* __restrict__ xin,
                                                     float* __restrict__ out,
                                                     __half2* __restrict__ outh) {
    extern __shared__ char sm[];
    uint32_t smb = smem_u32(sm);
    int tid = threadIdx.x;
    int row0 = blockIdx.x * MT;

    int m = tid >> 2, q = tid & 3;             // 128 rows x 4 quarter-threads
    bool valid = (row0 + m) < NN;
    int rowc = min(row0 + m, NN - 1);          // clamp: loads always in-bounds
    const __half2* hrow = hh + (size_t)rowc * 64;
    const __half2* arow = agg + (size_t)rowc * 64;

    const uint32_t aoff[2] = {0u, (uint32_t)A_TILE};
    uint32_t fbase = (uint32_t)(m * (LDAE * 2) + q * 32);

    uint32_t fr[8];                            // 16 half = this thread's k-slice
    const __half2 H2_ONE = __floats2half2_rn(1.0f, 1.0f);
    const __half2 H2_NL2E = __floats2half2_rn(-1.4426950408889634f, -1.4426950408889634f);

    auto gen = [&](int c) {                    // c compile-time after unroll
        const __half2* r = (c < 18) ? hrow : arow;
        int cs = (c < 18) ? c : c - 18;
        if (cs < 2) {                          // silu chunk: 16 values, pure half2
#pragma unroll
            for (int g = 0; g < 2; g++) {
                uint4 u = *(const uint4*)(r + cs * 32 + q * 8 + g * 4);
                uint32_t uw[4] = {u.x, u.y, u.z, u.w};
#pragma unroll
                for (int i = 0; i < 4; i++) {
                    __half2 h = *(__half2*)&uw[i];
                    __half2 e = h2exp2(__hmul2(h, H2_NL2E));       // exp(-h)
                    __half2 s = __hmul2(h, h2rcp(__hadd2(H2_ONE, e)));
                    fr[g * 4 + i] = *(uint32_t*)&s;
                }
            }
        } else {                               // spline chunk: 2 dims x 8 bases
            float2 f = __half22float2(r[(cs - 2) * 4 + q]);
            bs8_fast(f.x, fr);
            bs8_fast(f.y, fr + 4);
        }
    };
    auto sts = [&](int buf) {
        uint32_t base = smb + aoff[buf] + fbase;
        asm volatile("st.shared.v4.b32 [%0], {%1,%2,%3,%4};"
                     :: "r"(base), "r"(fr[0]), "r"(fr[1]), "r"(fr[2]), "r"(fr[3]));
        asm volatile("st.shared.v4.b32 [%0], {%1,%2,%3,%4};"
                     :: "r"(base + 16), "r"(fr[4]), "r"(fr[5]), "r"(fr[6]), "r"(fr[7]));
    };
    auto ldb = [&](int buf, int c) {           // one commit group per call
        const char* src = (const char*)(g_wt) + (size_t)c * 64 * DD * 2;
        uint32_t bb = smb + (uint32_t)(2 * A_TILE + buf * B_TILE);
#pragma unroll
        for (int qq = 0; qq < 2; qq++) {
            int i = tid + qq * NTHR;
            int r = i >> 4, c16 = i & 15;
            cp_async16(bb + r * (LDBE * 2) + c16 * 16, src + i * 16);
        }
        cp_commit();
    };

    int warp = tid >> 5;
    int m0 = (warp & 3) * 32, n0 = (warp >> 2) * 32;   // 4x4 warp grid, 32x32 tiles
    wmma::fragment<wmma::accumulator, 16, 16, 16, __half> acc[2][2];
#pragma unroll
    for (int i = 0; i < 2; i++)
#pragma unroll
        for (int j = 0; j < 2; j++) wmma::fill_fragment(acc[i][j], __float2half(0.0f));

    // prologue: A buf0 + B chunks 0..2 in flight
    gen(0); sts(0);
    ldb(0, 0); ldb(1, 1); ldb(2, 2);

#pragma unroll
    for (int c = 0; c < NCH; c++) {            // FULL unroll: c compile-time
        const int ca = c & 1, na = ca ^ 1;
        if (c + 1 < NCH) gen(c + 1);
        cp_wait2();                             // B(c) complete (2 newer may pend)
        __syncthreads();                        // B buf (c+3)&3 free; A(c) visible
        if (c + 3 < NCH) ldb((c + 3) & 3, c + 3);
        else cp_commit();                       // empty group keeps count aligned
        if (c + 1 < NCH) sts(na);

        const __half* As = (const __half*)(sm + aoff[ca]);
        const __half* Bs = (const __half*)(sm + 2 * A_TILE + (c & 3) * B_TILE);
#pragma unroll
        for (int kk = 0; kk < 4; kk++) {
            wmma::fragment<wmma::matrix_a, 16, 16, 16, __half, wmma::row_major> a0, a1;
            wmma::load_matrix_sync(a0, As + m0 * LDAE + kk * 16, LDAE);
            wmma::load_matrix_sync(a1, As + (m0 + 16) * LDAE + kk * 16, LDAE);
#pragma unroll
            for (int j = 0; j < 2; j++) {
                wmma::fragment<wmma::matrix_b, 16, 16, 16, __half, wmma::row_major> bf;
                wmma::load_matrix_sync(bf, Bs + kk * 16 * LDBE + n0 + j * 16, LDBE);
                wmma::mma_sync(acc[0][j], a0, bf, acc[0][j]);
                wmma::mma_sync(acc[1][j], a1, bf, acc[1][j]);
            }
        }
    }

    // epilogue: stage half tile (128 x LDCE), fused Euler update + half mirror
    __syncthreads();
    __half* cs = (__half*)sm;
#pragma unroll
    for (int i = 0; i < 2; i++)
#pragma unroll
        for (int j = 0; j < 2; j++)
            wmma::store_matrix_sync(cs + (m0 + i * 16) * LDCE + n0 + j * 16, acc[i][j],
                                    LDCE, wmma::mem_row_major);
    __syncthreads();

    if (valid) {
        const __half2* crow = (const __half2*)(cs + m * LDCE + q * 32);
        float4* po = (float4*)(out + (size_t)(row0 + m) * DD + q * 32);
        const float4* xr = (const float4*)(xin + (size_t)(row0 + m) * DD + q * 32);
        uint2* ph = (uint2*)(outh + (size_t)(row0 + m) * 64 + q * 16);
#pragma unroll
        for (int g = 0; g < 8; g++) {
            float2 a0 = __half22float2(crow[g * 2]);
            float2 a1 = __half22float2(crow[g * 2 + 1]);
            float4 x4 = xr[g];
            float4 o = make_float4(x4.x + EPSI * a0.x, x4.y + EPSI * a0.y,
                                   x4.z + EPSI * a1.x, x4.w + EPSI * a1.y);
            po[g] = o;
            if (WH) {
                __half2 h0 = __floats2half2_rn(o.x, o.y);
                __half2 h1 = __floats2half2_rn(o.z, o.w);
                ph[g] = make_uint2(*(uint32_t*)&h0, *(uint32_t*)&h1);
            }
        }
    }
}

// ---------------- half scatter: agg[dst] += rsqrt(ds+1)rsqrt(dd+1) * h[src] ----
__global__ void scatter_half(const uint4* __restrict__ hh, const void* __restrict__ ei,
                             __half2* __restrict__ agg) {
    long long gid = (long long)blockIdx.x * blockDim.x + threadIdx.x;
    long long e = gid >> 4;
    int lane = (int)(gid & 15);
    if (e >= EE) return;
    int src = get_idx(ei, e);
    int dst = get_idx(ei, (long long)EE + e);
    float nrm = rsqrtf(g_deg[src] + 1.0f) * rsqrtf(g_deg[dst] + 1.0f);
    __half2 nh = __float2half2_rn(nrm);
    uint4 v = hh[(size_t)src * 16 + lane];
    __half2 a0 = __hmul2(*(__half2*)&v.x, nh);
    __half2 a1 = __hmul2(*(__half2*)&v.y, nh);
    __half2 a2 = __hmul2(*(__half2*)&v.z, nh);
    __half2 a3 = __hmul2(*(__half2*)&v.w, nh);
    __half2* p = agg + (size_t)dst * 64 + lane * 4;
    asm volatile("red.global.add.noftz.v4.f16x2 [%0], {%1,%2,%3,%4};"
                 :: "l"(p), "r"(*(uint32_t*)&a0), "r"(*(uint32_t*)&a1),
                    "r"(*(uint32_t*)&a2), "r"(*(uint32_t*)&a3) : "memory");
}

// ---------------- launch -------------------------------------------------------
extern "C" void kernel_launch(void* const* d_in, const int* in_sizes, int n_in,
                              void* d_out, int out_size) {
    const float* x = (const float*)d_in[0];
    const void* ei = d_in[1];
    const float* bwl = (const float*)d_in[2];
    const float* swl = (const float*)d_in[3];
    const float* bwc = (const float*)d_in[4];
    const float* swc = (const float*)d_in[5];
    float* out = (float*)d_out;

    cudaFuncSetAttribute(kan_fused<0>, cudaFuncAttributeMaxDynamicSharedMemorySize, KAN_SMEM);
    cudaFuncSetAttribute(kan_fused<1>, cudaFuncAttributeMaxDynamicSharedMemorySize, KAN_SMEM);

    void *xp, *xhp, *aggp;
    cudaGetSymbolAddress(&xp, g_x);
    cudaGetSymbolAddress(&xhp, g_xh);
    cudaGetSymbolAddress(&aggp, g_aggh);
    float* gx = (float*)xp;
    __half2* gxh = (__half2*)xhp;
    __half2* agg0 = (__half2*)aggp;
    __half2* agg1 = agg0 + (size_t)NN * 64;

    const int GRID_KAN = (NN + MT - 1) / MT;   // 391

    // launches: 1 setup  2 deg  3 scatter0  4 kan0 (ncu capture)  5 scatter1  6 kan1
    setup_kernel<<<(int)((N_SETUP + 255) / 256), 256>>>(x, bwl, swl, bwc, swc, (const int*)ei);
    deg_kernel<<<(EE + 255) / 256, 256>>>(ei);

    scatter_half<<<(int)((EE * 16LL + 255) / 256), 256>>>((const uint4*)gxh, ei, agg0);
    kan_fused<1><<<GRID_KAN, NTHR, KAN_SMEM>>>(gxh, agg0, x, gx, gxh);

    scatter_half<<<(int)((EE * 16LL + 255) / 256), 256>>>((const uint4*)gxh, ei, agg1);
    kan_fused<0><<<GRID_KAN, NTHR, KAN_SMEM>>>(gxh, agg1, gx, out, gxh);
}

// round 10
// speedup vs baseline: 1.0373x; 1.0373x over previous
#include <cuda_runtime.h>
#include <cuda_fp16.h>
#include <mma.h>
#include <cstdint>

using namespace nvcuda;

#define NN 50000
#define EE 800000
#define DD 128
#define EPSI 0.001f
#define NCH 36                     // K = 2304 = 36 * 64 (18 per weight set)
#define MT 128                     // M tile rows per CTA
#define NTHR 512
#define LDAE 72                    // A tile ld (halfs), 144 B
#define LDBE 136                   // B tile ld (halfs), 272 B
#define LDCE 136                   // epilogue staging ld (halfs)
#define A_TILE (MT * LDAE * 2)     // 18432 B
#define B_TILE (64 * LDBE * 2)     // 17408 B
#define NBUF 3                     // B pipeline depth (89 KB smem -> 50 KB L1 kept)
#define KAN_SMEM (2 * A_TILE + NBUF * B_TILE)  // 89088 B

// ---------------- device scratch ----------------------------------------------
__device__ float g_x[(size_t)NN * DD];
__device__ __half2 g_xh[(size_t)NN * 64];
__device__ __half2 g_aggh[2][(size_t)NN * 64];
__device__ float g_deg[NN];
__device__ __half g_wt[2 * 1152 * DD];  // [set][k][o], k-major (36 chunks of 64 k)
__device__ int g_is64;

// ---------------- helpers ------------------------------------------------------
__device__ __forceinline__ uint32_t smem_u32(const void* p) {
    uint32_t a;
    asm("{ .reg .u64 t; cvta.to.shared.u64 t, %1; cvt.u32.u64 %0, t; }" : "=r"(a) : "l"(p));
    return a;
}
__device__ __forceinline__ void cp_async16(uint32_t dst, const void* src) {
    asm volatile("cp.async.cg.shared.global [%0], [%1], 16;" :: "r"(dst), "l"(src));
}
__device__ __forceinline__ void cp_commit() { asm volatile("cp.async.commit_group;"); }
__device__ __forceinline__ void cp_wait1() { asm volatile("cp.async.wait_group 1;"); }
__device__ __forceinline__ unsigned pack2h(float a, float b) {
    __half2 h = __floats2half2_rn(a, b);
    return *(unsigned*)&h;
}
__device__ __forceinline__ int get_idx(const void* p, long long e) {
    if (g_is64) return (int)((const long long*)p)[e];
    return ((const int*)p)[e];
}

// ---------------- local cubic B-spline: 4 nonzero bases -> 4 packed u32 -------
__device__ __forceinline__ void bs8_fast(float x, uint32_t* w) {
    float T = fmaf(x, 2.5f, 5.5f);
    T = fminf(fmaxf(T, 2.0f), 8.999f);
    float jf = floorf(T);
    float u = T - jf;
    int s = (int)jf - 3;
    float u2 = u * u, u3 = u2 * u;
    float v0 = fmaf(u, -0.5f, 1.0f / 6.0f);
    v0 = fmaf(u2, 0.5f, v0);
    v0 = fmaf(u3, -1.0f / 6.0f, v0);
    float v1 = fmaf(u2, -1.0f, 2.0f / 3.0f);
    v1 = fmaf(u3, 0.5f, v1);
    float v2 = fmaf(u, 0.5f, 1.0f / 6.0f);
    v2 = fmaf(u2, 0.5f, v2);
    v2 = fmaf(u3, -0.5f, v2);
    float v3 = u3 * (1.0f / 6.0f);
    uint32_t p01 = pack2h(v0, v1), p23 = pack2h(v2, v3);
    int sh = (s & 1) << 4;
    int p = s >> 1;
    uint32_t r0 = p01 << sh;
    uint32_t r1 = __funnelshift_l(p01, p23, sh);
    uint32_t r2 = sh ? (p23 >> 16) : 0u;
#pragma unroll
    for (int i = 0; i < 4; i++) {
        int d = i - p;
        w[i] = (d == 0) ? r0 : (d == 1) ? r1 : (d == 2) ? r2 : 0u;
    }
}

// ---------------- setup: x->half, clear agg/deg, weights->half, detect ---------
#define N_XH ((long long)NN * 32)
#define N_CLR ((long long)2 * NN * 16)
#define N_W ((long long)2 * 1152 * 128)
#define N_SETUP (N_XH + N_CLR + N_W + NN + 1)

__global__ void setup_kernel(const float* __restrict__ x,
                             const float* __restrict__ bwl, const float* __restrict__ swl,
                             const float* __restrict__ bwc, const float* __restrict__ swc,
                             const int* __restrict__ ei) {
    long long idx = (long long)blockIdx.x * 256 + threadIdx.x;
    if (idx < N_XH) {
        float4 v = ((const float4*)x)[idx];
        __half2 h0 = __floats2half2_rn(v.x, v.y);
        __half2 h1 = __floats2half2_rn(v.z, v.w);
        ((uint2*)g_xh)[idx] = make_uint2(*(uint32_t*)&h0, *(uint32_t*)&h1);
    } else if (idx < N_XH + N_CLR) {
        ((uint4*)g_aggh)[idx - N_XH] = make_uint4(0, 0, 0, 0);
    } else if (idx < N_XH + N_CLR + N_W) {
        long long r = idx - N_XH - N_CLR;
        int set = (int)(r / (1152 * 128));
        int q = (int)(r - (long long)set * (1152 * 128));
        int k = q >> 7, o = q & 127;
        const float* bw = set ? bwc : bwl;
        const float* sw = set ? swc : swl;
        float v = (k < DD) ? bw[o * DD + k] : sw[(long long)o * 1024 + (k - DD)];
        g_wt[r] = __float2half(v);
    } else if (idx < N_XH + N_CLR + N_W + NN) {
        g_deg[idx - N_XH - N_CLR - N_W] = 0.0f;
    } else if (idx == N_XH + N_CLR + N_W + NN) {
        int is64 = 1;
        for (int k = 0; k < 16; k++)
            if (ei[2 * k + 1] != 0) { is64 = 0; break; }
        g_is64 = is64;
    }
}

__global__ void deg_kernel(const void* __restrict__ ei) {
    int e = blockIdx.x * blockDim.x + threadIdx.x;
    if (e < EE) atomicAdd(&g_deg[get_idx(ei, (long long)EE + e)], 1.0f);
}

// ---------------- fused dual-branch KAN kernel (MT=128, 512 thr, fp16 acc) -----
// out = xin + EPSI * ( featL(xh)@WL + featC(agg)@WC )
// Fully-unrolled chunk loop; 3-stage cp.async pipeline on B tiles.
template <int WH>
__global__ __launch_bounds__(NTHR, 2) void kan_fused(const __half2* __restrict__ hh,
                                                     const __half2* __restrict__ agg,
                                                     const float* __restrict__ xin,
                                                     float* __restrict__ out,
                                                     __half2* __restrict__ outh) {
    extern __shared__ char sm[];
    uint32_t smb = smem_u32(sm);
    int tid = threadIdx.x;
    int row0 = blockIdx.x * MT;

    int m = tid >> 2, q = tid & 3;             // 128 rows x 4 quarter-threads
    bool valid = (row0 + m) < NN;
    int rowc = min(row0 + m, NN - 1);          // clamp: loads always in-bounds
    const __half2* hrow = hh + (size_t)rowc * 64;
    const __half2* arow = agg + (size_t)rowc * 64;

    const uint32_t aoff[2] = {0u, (uint32_t)A_TILE};
    uint32_t fbase = (uint32_t)(m * (LDAE * 2) + q * 32);

    uint32_t fr[8];                            // 16 half = this thread's k-slice
    const __half2 H2_ONE = __floats2half2_rn(1.0f, 1.0f);
    const __half2 H2_NL2E = __floats2half2_rn(-1.4426950408889634f, -1.4426950408889634f);

    auto gen = [&](int c) {                    // c compile-time after unroll
        const __half2* r = (c < 18) ? hrow : arow;
        int cs = (c < 18) ? c : c - 18;
        if (cs < 2) {                          // silu chunk: 16 values, pure half2
#pragma unroll
            for (int g = 0; g < 2; g++) {
                uint4 u = *(const uint4*)(r + cs * 32 + q * 8 + g * 4);
                uint32_t uw[4] = {u.x, u.y, u.z, u.w};
#pragma unroll
                for (int i = 0; i < 4; i++) {
                    __half2 h = *(__half2*)&uw[i];
                    __half2 e = h2exp2(__hmul2(h, H2_NL2E));       // exp(-h)
                    __half2 s = __hmul2(h, h2rcp(__hadd2(H2_ONE, e)));
                    fr[g * 4 + i] = *(uint32_t*)&s;
                }
            }
        } else {                               // spline chunk: 2 dims x 8 bases
            float2 f = __half22float2(r[(cs - 2) * 4 + q]);
            bs8_fast(f.x, fr);
            bs8_fast(f.y, fr + 4);
        }
    };
    auto sts = [&](int buf) {
        uint32_t base = smb + aoff[buf] + fbase;
        asm volatile("st.shared.v4.b32 [%0], {%1,%2,%3,%4};"
                     :: "r"(base), "r"(fr[0]), "r"(fr[1]), "r"(fr[2]), "r"(fr[3]));
        asm volatile("st.shared.v4.b32 [%0], {%1,%2,%3,%4};"
                     :: "r"(base + 16), "r"(fr[4]), "r"(fr[5]), "r"(fr[6]), "r"(fr[7]));
    };
    auto ldb = [&](int buf, int c) {           // one commit group per call
        const char* src = (const char*)(g_wt) + (size_t)c * 64 * DD * 2;
        uint32_t bb = smb + (uint32_t)(2 * A_TILE + buf * B_TILE);
#pragma unroll
        for (int qq = 0; qq < 2; qq++) {
            int i = tid + qq * NTHR;
            int r = i >> 4, c16 = i & 15;
            cp_async16(bb + r * (LDBE * 2) + c16 * 16, src + i * 16);
        }
        cp_commit();
    };

    int warp = tid >> 5;
    int m0 = (warp & 3) * 32, n0 = (warp >> 2) * 32;   // 4x4 warp grid, 32x32 tiles
    wmma::fragment<wmma::accumulator, 16, 16, 16, __half> acc[2][2];
#pragma unroll
    for (int i = 0; i < 2; i++)
#pragma unroll
        for (int j = 0; j < 2; j++) wmma::fill_fragment(acc[i][j], __float2half(0.0f));

    // prologue: A buf0 + B chunks 0..1 in flight
    gen(0); sts(0);
    ldb(0, 0); ldb(1, 1);

#pragma unroll
    for (int c = 0; c < NCH; c++) {            // FULL unroll: c compile-time
        const int ca = c & 1, na = ca ^ 1;
        if (c + 1 < NCH) gen(c + 1);
        cp_wait1();                             // B(c) complete (1 newer may pend)
        __syncthreads();                        // B buf (c+2)%3 free; A(c) visible
        if (c + 2 < NCH) ldb((c + 2) % NBUF, c + 2);
        else cp_commit();                       // empty group keeps count aligned
        if (c + 1 < NCH) sts(na);

        const __half* As = (const __half*)(sm + aoff[ca]);
        const __half* Bs = (const __half*)(sm + 2 * A_TILE + (c % NBUF) * B_TILE);
#pragma unroll
        for (int kk = 0; kk < 4; kk++) {
            wmma::fragment<wmma::matrix_a, 16, 16, 16, __half, wmma::row_major> a0, a1;
            wmma::load_matrix_sync(a0, As + m0 * LDAE + kk * 16, LDAE);
            wmma::load_matrix_sync(a1, As + (m0 + 16) * LDAE + kk * 16, LDAE);
#pragma unroll
            for (int j = 0; j < 2; j++) {
                wmma::fragment<wmma::matrix_b, 16, 16, 16, __half, wmma::row_major> bf;
                wmma::load_matrix_sync(bf, Bs + kk * 16 * LDBE + n0 + j * 16, LDBE);
                wmma::mma_sync(acc[0][j], a0, bf, acc[0][j]);
                wmma::mma_sync(acc[1][j], a1, bf, acc[1][j]);
            }
        }
    }

    // epilogue: stage half tile (128 x LDCE), fused Euler update + half mirror
    __syncthreads();
    __half* cs = (__half*)sm;
#pragma unroll
    for (int i = 0; i < 2; i++)
#pragma unroll
        for (int j = 0; j < 2; j++)
            wmma::store_matrix_sync(cs + (m0 + i * 16) * LDCE + n0 + j * 16, acc[i][j],
                                    LDCE, wmma::mem_row_major);
    __syncthreads();

    if (valid) {
        const __half2* crow = (const __half2*)(cs + m * LDCE + q * 32);
        float4* po = (float4*)(out + (size_t)(row0 + m) * DD + q * 32);
        const float4* xr = (const float4*)(xin + (size_t)(row0 + m) * DD + q * 32);
        uint2* ph = (uint2*)(outh + (size_t)(row0 + m) * 64 + q * 16);
#pragma unroll
        for (int g = 0; g < 8; g++) {
            float2 a0 = __half22float2(crow[g * 2]);
            float2 a1 = __half22float2(crow[g * 2 + 1]);
            float4 x4 = xr[g];
            float4 o = make_float4(x4.x + EPSI * a0.x, x4.y + EPSI * a0.y,
                                   x4.z + EPSI * a1.x, x4.w + EPSI * a1.y);
            po[g] = o;
            if (WH) {
                __half2 h0 = __floats2half2_rn(o.x, o.y);
                __half2 h1 = __floats2half2_rn(o.z, o.w);
                ph[g] = make_uint2(*(uint32_t*)&h0, *(uint32_t*)&h1);
            }
        }
    }
}

// ---------------- half scatter: agg[dst] += rsqrt(ds+1)rsqrt(dd+1) * h[src] ----
__global__ void scatter_half(const uint4* __restrict__ hh, const void* __restrict__ ei,
                             __half2* __restrict__ agg) {
    long long gid = (long long)blockIdx.x * blockDim.x + threadIdx.x;
    long long e = gid >> 4;
    int lane = (int)(gid & 15);
    if (e >= EE) return;
    int src = get_idx(ei, e);
    int dst = get_idx(ei, (long long)EE + e);
    float nrm = rsqrtf(g_deg[src] + 1.0f) * rsqrtf(g_deg[dst] + 1.0f);
    __half2 nh = __float2half2_rn(nrm);
    uint4 v = hh[(size_t)src * 16 + lane];
    __half2 a0 = __hmul2(*(__half2*)&v.x, nh);
    __half2 a1 = __hmul2(*(__half2*)&v.y, nh);
    __half2 a2 = __hmul2(*(__half2*)&v.z, nh);
    __half2 a3 = __hmul2(*(__half2*)&v.w, nh);
    __half2* p = agg + (size_t)dst * 64 + lane * 4;
    asm volatile("red.global.add.noftz.v4.f16x2 [%0], {%1,%2,%3,%4};"
                 :: "l"(p), "r"(*(uint32_t*)&a0), "r"(*(uint32_t*)&a1),
                    "r"(*(uint32_t*)&a2), "r"(*(uint32_t*)&a3) : "memory");
}

// ---------------- launch -------------------------------------------------------
extern "C" void kernel_launch(void* const* d_in, const int* in_sizes, int n_in,
                              void* d_out, int out_size) {
    const float* x = (const float*)d_in[0];
    const void* ei = d_in[1];
    const float* bwl = (const float*)d_in[2];
    const float* swl = (const float*)d_in[3];
    const float* bwc = (const float*)d_in[4];
    const float* swc = (const float*)d_in[5];
    float* out = (float*)d_out;

    cudaFuncSetAttribute(kan_fused<0>, cudaFuncAttributeMaxDynamicSharedMemorySize, KAN_SMEM);
    cudaFuncSetAttribute(kan_fused<1>, cudaFuncAttributeMaxDynamicSharedMemorySize, KAN_SMEM);

    void *xp, *xhp, *aggp;
    cudaGetSymbolAddress(&xp, g_x);
    cudaGetSymbolAddress(&xhp, g_xh);
    cudaGetSymbolAddress(&aggp, g_aggh);
    float* gx = (float*)xp;
    __half2* gxh = (__half2*)xhp;
    __half2* agg0 = (__half2*)aggp;
    __half2* agg1 = agg0 + (size_t)NN * 64;

    const int GRID_KAN = (NN + MT - 1) / MT;   // 391

    // launches: 1 setup  2 deg  3 scatter0  4 kan0 (ncu capture)  5 scatter1  6 kan1
    setup_kernel<<<(int)((N_SETUP + 255) / 256), 256>>>(x, bwl, swl, bwc, swc, (const int*)ei);
    deg_kernel<<<(EE + 255) / 256, 256>>>(ei);

    scatter_half<<<(int)((EE * 16LL + 255) / 256), 256>>>((const uint4*)gxh, ei, agg0);
    kan_fused<1><<<GRID_KAN, NTHR, KAN_SMEM>>>(gxh, agg0, x, gx, gxh);

    scatter_half<<<(int)((EE * 16LL + 255) / 256), 256>>>((const uint4*)gxh, ei, agg1);
    kan_fused<0><<<GRID_KAN, NTHR, KAN_SMEM>>>(gxh, agg1, gx, out, gxh);
}